// round 14
// baseline (speedup 1.0000x reference)
#include <cuda_runtime.h>
#include <cuda_fp16.h>
#include <math.h>
#include <stdint.h>

#define T_TOK 2048
#define Dm    512
#define Hm    1024
#define Em    8
#define CAP   2048

// ---------------- scratch (static device globals) ----------------
__device__ int   g_count[Em];
__device__ int   g_list[Em * CAP];
__device__ float g_wt[2 * T_TOK];

__device__ __align__(16) __half g_w1h[Em * Hm * Dm];
__device__ __align__(16) __half g_w2h[Em * Dm * Hm];
__device__ __align__(16) __half g_xh[Em * CAP * Dm];
__device__ __align__(16) __half g_hh[Em * CAP * Hm];

// ---------------- PTX helpers ----------------
__device__ __forceinline__ uint32_t smem_u32(const void* p) {
    uint32_t a;
    asm("{ .reg .u64 t; cvta.to.shared.u64 t, %1; cvt.u32.u64 %0, t; }" : "=r"(a) : "l"(p));
    return a;
}
__device__ __forceinline__ void cp16(uint32_t dst, const void* src) {
    asm volatile("cp.async.cg.shared.global [%0], [%1], 16;" :: "r"(dst), "l"(src));
}
#define CP_COMMIT() asm volatile("cp.async.commit_group;" ::: "memory")
#define CP_WAIT(n)  asm volatile("cp.async.wait_group %0;" :: "n"(n) : "memory")

__device__ __forceinline__ uint32_t swz(uint32_t off) { return off ^ ((off >> 3) & 0x70); }

__device__ __forceinline__ void ldm_x4(uint32_t* r, uint32_t addr) {
    asm volatile("ldmatrix.sync.aligned.m8n8.x4.shared.b16 {%0,%1,%2,%3}, [%4];"
                 : "=r"(r[0]), "=r"(r[1]), "=r"(r[2]), "=r"(r[3]) : "r"(addr));
}
__device__ __forceinline__ void mma16816(float* c, const uint32_t* a, uint32_t b0, uint32_t b1) {
    asm volatile("mma.sync.aligned.m16n8k16.row.col.f32.f16.f16.f32 "
                 "{%0,%1,%2,%3}, {%4,%5,%6,%7}, {%8,%9}, {%0,%1,%2,%3};"
                 : "+f"(c[0]), "+f"(c[1]), "+f"(c[2]), "+f"(c[3])
                 : "r"(a[0]), "r"(a[1]), "r"(a[2]), "r"(a[3]), "r"(b0), "r"(b1));
}

// 128-row x 64-col fp16 tile -> SW128 swizzled smem (256 threads, 4 iters)
__device__ __forceinline__ void stage_tile128(uint32_t sbase, const __half* src,
                                              int stride, int tid) {
#pragma unroll
    for (int q4 = 0; q4 < 4; q4++) {
        int q = tid + q4 * 256;
        int r = q >> 3, c = q & 7;
        cp16(sbase + swz((uint32_t)(r * 128 + c * 16)), src + (size_t)r * stride + c * 8);
    }
}

// ---------------- helpers for prep ----------------
__device__ __forceinline__ void conv_two(const float* src, __half* hi, int g0) {
    const int g1 = g0 + 256;
    const float4* s0 = (const float4*)src + (size_t)g0 * 2;
    const float4* s1 = (const float4*)src + (size_t)g1 * 2;
    float4 a0 = s0[0], b0 = s0[1], a1 = s1[0], b1 = s1[1];
    float f0[8] = {a0.x, a0.y, a0.z, a0.w, b0.x, b0.y, b0.z, b0.w};
    float f1[8] = {a1.x, a1.y, a1.z, a1.w, b1.x, b1.y, b1.z, b1.w};
    alignas(16) __half h0[8], h1[8];
#pragma unroll
    for (int j = 0; j < 8; j++) h0[j] = __float2half_rn(f0[j]);
#pragma unroll
    for (int j = 0; j < 8; j++) h1[j] = __float2half_rn(f1[j]);
    *(uint4*)(hi + (size_t)g0 * 8) = *(uint4*)h0;
    *(uint4*)(hi + (size_t)g1 * 8) = *(uint4*)h1;
}

// w2 conversion only (side stream, overlapped with router/w1/fc1a)
__global__ __launch_bounds__(256) void convw2_kernel(const float* __restrict__ w2) {
    conv_two(w2, g_w2h, blockIdx.x * 512 + threadIdx.x);
}

__global__ void finish_kernel() {}

// ---------------- fused router + w1 conversion ----------------
__global__ __launch_bounds__(256) void prep_router_kernel(const float* __restrict__ x,
                                                          const float* __restrict__ wr,
                                                          const float* __restrict__ br,
                                                          const float* __restrict__ w1,
                                                          float* __restrict__ logits_out) {
    const int b = blockIdx.x;
    if (b >= 128) {
        conv_two(w1, g_w1h, (b - 128) * 512 + threadIdx.x);
        return;
    }

    const int warp = threadIdx.x >> 5;
    const int lane = threadIdx.x & 31;
    const int t0 = (b * 8 + warp) * 2;

    float4 xv[2][4];
#pragma unroll
    for (int s = 0; s < 2; s++) {
        const float4* xv4 = (const float4*)(x) + (size_t)(t0 + s) * (Dm / 4);
#pragma unroll
        for (int i = 0; i < 4; i++) xv[s][i] = xv4[i * 32 + lane];
    }

    float acc[2][Em];
#pragma unroll
    for (int e = 0; e < Em; e++) {
        const float4* wv4 = (const float4*)(wr) + (size_t)e * (Dm / 4);
        float4 wv[4];
#pragma unroll
        for (int i = 0; i < 4; i++) wv[i] = wv4[i * 32 + lane];
#pragma unroll
        for (int s = 0; s < 2; s++) {
            float a = 0.f;
#pragma unroll
            for (int i = 0; i < 4; i++)
                a += xv[s][i].x * wv[i].x + xv[s][i].y * wv[i].y
                   + xv[s][i].z * wv[i].z + xv[s][i].w * wv[i].w;
            acc[s][e] = a;
        }
    }
#pragma unroll
    for (int off = 16; off > 0; off >>= 1)
#pragma unroll
        for (int s = 0; s < 2; s++)
#pragma unroll
            for (int e = 0; e < Em; e++)
                acc[s][e] += __shfl_xor_sync(0xffffffffu, acc[s][e], off);

#pragma unroll
    for (int s = 0; s < 2; s++) {
        const int t = t0 + s;
        float* lg = acc[s];
#pragma unroll
        for (int e = 0; e < Em; e++) lg[e] += br[e];

        int pack0 = 0, pack1 = 0;
        if (lane == 0) {
            *(float4*)(logits_out + (size_t)t * Em)     = make_float4(lg[0], lg[1], lg[2], lg[3]);
            *(float4*)(logits_out + (size_t)t * Em + 4) = make_float4(lg[4], lg[5], lg[6], lg[7]);
            float mx = lg[0];
#pragma unroll
            for (int e = 1; e < Em; e++) mx = fmaxf(mx, lg[e]);
            float p[Em]; float sum = 0.f;
#pragma unroll
            for (int e = 0; e < Em; e++) { p[e] = expf(lg[e] - mx); sum += p[e]; }
            float inv = 1.0f / sum;
#pragma unroll
            for (int e = 0; e < Em; e++) p[e] *= inv;
            int e0 = 0;
#pragma unroll
            for (int e = 1; e < Em; e++) if (p[e] > p[e0]) e0 = e;
            int e1 = (e0 == 0) ? 1 : 0;
#pragma unroll
            for (int e = 0; e < Em; e++) if (e != e0 && p[e] > p[e1]) e1 = e;
            float sum2 = p[e0] + p[e1];
            g_wt[2 * t + 0] = p[e0] / sum2;
            g_wt[2 * t + 1] = p[e1] / sum2;
            int pos0 = atomicAdd(&g_count[e0], 1);
            g_list[e0 * CAP + pos0] = 2 * t + 0;
            int pos1 = atomicAdd(&g_count[e1], 1);
            g_list[e1 * CAP + pos1] = 2 * t + 1;
            pack0 = (e0 << 16) | pos0;
            pack1 = (e1 << 16) | pos1;
        }
        pack0 = __shfl_sync(0xffffffffu, pack0, 0);
        pack1 = __shfl_sync(0xffffffffu, pack1, 0);
        const int e0 = pack0 >> 16, pos0 = pack0 & 0xffff;
        const int e1 = pack1 >> 16, pos1 = pack1 & 0xffff;

        __half* dh0 = g_xh + ((size_t)e0 * CAP + pos0) * Dm;
        __half* dh1 = g_xh + ((size_t)e1 * CAP + pos1) * Dm;
#pragma unroll
        for (int i = 0; i < 4; i++) {
            float f[4] = {xv[s][i].x, xv[s][i].y, xv[s][i].z, xv[s][i].w};
            alignas(8) __half h[4];
#pragma unroll
            for (int j = 0; j < 4; j++) h[j] = __float2half_rn(f[j]);
            int eo = (i * 32 + lane) * 4;
            *(uint2*)(dh0 + eo) = *(uint2*)h;
            *(uint2*)(dh1 + eo) = *(uint2*)h;
        }
    }
}

// ---------------- GEMM mainloop: 256 thr, CTA 128x128, 3 buffers, occ 2 ----------------
// One barrier per k-tile (bottom sync removed: next iteration's top barrier already
// orders all compute on buf(i) before anyone stages into it). Warp-staggered kk order.
extern __shared__ char smx[];

#define STAGE_J(kt, bufi)                                                             \
    do {                                                                              \
        uint32_t sb2_ = smb + (bufi) * 32768;                                         \
        stage_tile128(sb2_,         Abase + aoff + (kt) * 64, STRIDE, tid);           \
        stage_tile128(sb2_ + 16384, Bbase + boff + (kt) * 64, STRIDE, tid);           \
        CP_COMMIT();                                                                  \
    } while (0)

#define GEMM_MAINLOOP(NT, STRIDE_V, JOFF)                                             \
    enum { STRIDE = STRIDE_V };                                                       \
    uint32_t smb = smem_u32(smx);                                                     \
    STAGE_J((JOFF) + 0, 0);                                                           \
    STAGE_J((JOFF) + 1, 1);                                                           \
    float acc[4][4][4];                                                               \
    _Pragma("unroll") for (int a1 = 0; a1 < 4; a1++)                                  \
    _Pragma("unroll") for (int a2 = 0; a2 < 4; a2++)                                  \
    _Pragma("unroll") for (int a3 = 0; a3 < 4; a3++) acc[a1][a2][a3] = 0.f;           \
    const int lr = lane & 15, lc = lane >> 4;                                         \
    int bc = 0, bs = 2;                                                               \
    for (int i = 0; i < NT; i++) {                                                    \
        if (i < NT - 1) CP_WAIT(1); else CP_WAIT(0);                                  \
        __syncthreads();                                                              \
        if (i + 2 < NT) { STAGE_J((JOFF) + i + 2, bs); bs = (bs == 2) ? 0 : bs + 1; } \
        uint32_t sa = smb + bc * 32768, sbb = sa + 16384;                             \
        bc = (bc == 2) ? 0 : bc + 1;                                                  \
        _Pragma("unroll")                                                             \
        for (int kk16 = 0; kk16 < 4; kk16++) {                                        \
            const int kidx = (kk16 + warpM) & 3;                                      \
            uint32_t af[4][4];                                                        \
            _Pragma("unroll")                                                         \
            for (int mi = 0; mi < 4; mi++) {                                          \
                uint32_t off = (uint32_t)((warpM * 64 + mi * 16 + lr) * 128           \
                                          + (kidx * 2 + lc) * 16);                    \
                ldm_x4(af[mi], sa + swz(off));                                        \
            }                                                                         \
            uint32_t bfr[2][4];                                                       \
            _Pragma("unroll")                                                         \
            for (int nj = 0; nj < 2; nj++) {                                          \
                uint32_t off = (uint32_t)((warpN * 32 + nj * 16 + lr) * 128           \
                                          + (kidx * 2 + lc) * 16);                    \
                ldm_x4(bfr[nj], sbb + swz(off));                                      \
            }                                                                         \
            _Pragma("unroll")                                                         \
            for (int mi = 0; mi < 4; mi++)                                            \
                _Pragma("unroll")                                                     \
                for (int ni = 0; ni < 4; ni++) {                                      \
                    const int nj = ni >> 1, sub = ni & 1;                             \
                    mma16816(acc[mi][ni], af[mi], bfr[nj][sub], bfr[nj][sub + 2]);    \
                }                                                                     \
        }                                                                             \
    }

// ---------------- fc1: h = gelu(X @ W1^T), expert-half [ebase, ebase+4) ----------------
__global__ __launch_bounds__(256, 2) void fc1_kernel(int ebase) {
    const int e = ebase + blockIdx.z;
    const int cnt = g_count[e];
    const int rowbase = blockIdx.y * 128;
    if (rowbase >= cnt) return;
    const int nbase = blockIdx.x * 128;

    const int tid = threadIdx.x;
    const int wid = tid >> 5, lane = tid & 31;
    const int warpM = wid >> 2, warpN = wid & 3;

    const __half* Abase = g_xh;
    const __half* Bbase = g_w1h;
    const size_t aoff = ((size_t)e * CAP + rowbase) * Dm;
    const size_t boff = ((size_t)e * Hm + nbase) * Dm;

    GEMM_MAINLOOP(8, Dm, 0)

    const int r0 = lane >> 2, c0 = (lane & 3) * 2;
#pragma unroll
    for (int mi = 0; mi < 4; mi++) {
#pragma unroll
        for (int half = 0; half < 2; half++) {
            int row = rowbase + warpM * 64 + mi * 16 + r0 + half * 8;
            size_t rg = ((size_t)e * CAP + row) * Hm + nbase + warpN * 32 + c0;
#pragma unroll
            for (int ni = 0; ni < 4; ni++) {
                float v0 = acc[mi][ni][half * 2 + 0];
                float v1 = acc[mi][ni][half * 2 + 1];
                float gg0 = 0.5f * v0 * (1.0f + erff(v0 * 0.70710678118654752f));
                float gg1 = 0.5f * v1 * (1.0f + erff(v1 * 0.70710678118654752f));
                __half h0 = __float2half_rn(gg0);
                __half h1 = __float2half_rn(gg1);
                uint32_t hp = (uint32_t)*(uint16_t*)&h0 | ((uint32_t)*(uint16_t*)&h1 << 16);
                *(uint32_t*)(g_hh + rg + ni * 8) = hp;
            }
        }
    }
}

// ---------------- fc2: out[tok] += w * (H @ W2^T), split-K x2, expert-half ----------------
__global__ __launch_bounds__(256, 2) void fc2_kernel(float* __restrict__ out, int ebase) {
    const int e = ebase + blockIdx.z;
    const int cnt = g_count[e];
    const int rowbase = blockIdx.y * 128;
    if (rowbase >= cnt) return;
    const int ksplit = blockIdx.x >> 2;
    const int nbase = (blockIdx.x & 3) * 128;

    const int tid = threadIdx.x;
    const int wid = tid >> 5, lane = tid & 31;
    const int warpM = wid >> 2, warpN = wid & 3;

    const __half* Abase = g_hh;
    const __half* Bbase = g_w2h;
    const size_t aoff = ((size_t)e * CAP + rowbase) * Hm;
    const size_t boff = ((size_t)e * Dm + nbase) * Hm;

    GEMM_MAINLOOP(8, Hm, ksplit * 8)

    const int r0 = lane >> 2, c0 = (lane & 3) * 2;
#pragma unroll
    for (int mi = 0; mi < 4; mi++) {
#pragma unroll
        for (int half = 0; half < 2; half++) {
            int pos = rowbase + warpM * 64 + mi * 16 + r0 + half * 8;
            if (pos >= cnt) continue;
            int entry = g_list[e * CAP + pos];
            float w = g_wt[entry];
            int tok = entry >> 1;
            float* op = out + (size_t)tok * Dm + nbase + warpN * 32 + c0;
#pragma unroll
            for (int ni = 0; ni < 4; ni++) {
                atomicAdd(op + ni * 8,     w * acc[mi][ni][half * 2 + 0]);
                atomicAdd(op + ni * 8 + 1, w * acc[mi][ni][half * 2 + 1]);
            }
        }
    }
}

// ---------------- launch ----------------
extern "C" void kernel_launch(void* const* d_in, const int* in_sizes, int n_in,
                              void* d_out, int out_size) {
    const float* x  = (const float*)d_in[0];
    const float* wr = (const float*)d_in[1];
    const float* br = (const float*)d_in[2];
    const float* w1 = (const float*)d_in[3];
    const float* w2 = (const float*)d_in[4];
    float* out = (float*)d_out;
    float* logits = out + (size_t)T_TOK * Dm;

    static void* count_ptr = nullptr;
    static cudaStream_t s2 = nullptr;
    static cudaEvent_t evFork = nullptr, evA = nullptr, evW2 = nullptr, evD = nullptr;
    static int init_done = 0;
    if (!init_done) {
        cudaFuncSetAttribute(fc1_kernel, cudaFuncAttributeMaxDynamicSharedMemorySize, 98304);
        cudaFuncSetAttribute(fc2_kernel, cudaFuncAttributeMaxDynamicSharedMemorySize, 98304);
        cudaGetSymbolAddress(&count_ptr, g_count);
        cudaStreamCreateWithFlags(&s2, cudaStreamNonBlocking);
        cudaEventCreateWithFlags(&evFork, cudaEventDisableTiming);
        cudaEventCreateWithFlags(&evA, cudaEventDisableTiming);
        cudaEventCreateWithFlags(&evW2, cudaEventDisableTiming);
        cudaEventCreateWithFlags(&evD, cudaEventDisableTiming);
        init_done = 1;
    }

    dim3 g1(Hm / 128, CAP / 128, 4);           // per expert-half
    dim3 g2((Dm / 128) * 2, CAP / 128, 4);

    // main: counts memset; fork side stream
    cudaMemsetAsync(count_ptr, 0, Em * sizeof(int));
    cudaEventRecord(evFork, 0);
    cudaStreamWaitEvent(s2, evFork, 0);

    // s2: w2 conversion + out zeroing (overlap with router/w1/fc1a)
    convw2_kernel<<<1024, 256, 0, s2>>>(w2);
    cudaMemsetAsync(out, 0, (size_t)T_TOK * Dm * sizeof(float), s2);
    cudaEventRecord(evW2, s2);

    // main: router + w1 conv, then fc1 first half
    prep_router_kernel<<<1152, 256>>>(x, wr, br, w1, logits);
    fc1_kernel<<<g1, 256, 98304>>>(0);
    cudaEventRecord(evA, 0);

    // s2: fc2 first half (needs fc1a + w2h + zeroed out) — overlaps fc1b on main
    cudaStreamWaitEvent(s2, evA, 0);
    fc2_kernel<<<g2, 256, 98304, s2>>>(out, 0);
    cudaEventRecord(evD, s2);

    // main: fc1 second half, then fc2 second half (needs w2h/out from s2)
    fc1_kernel<<<g1, 256, 98304>>>(4);
    cudaStreamWaitEvent(0, evW2, 0);
    fc2_kernel<<<g2, 256, 98304>>>(out, 4);

    // join fc2a back into main before graph end
    cudaStreamWaitEvent(0, evD, 0);
    finish_kernel<<<1, 32>>>();
}

// round 15
// speedup vs baseline: 1.2828x; 1.2828x over previous
#include <cuda_runtime.h>
#include <cuda_fp16.h>
#include <math.h>
#include <stdint.h>

#define T_TOK 2048
#define Dm    512
#define Hm    1024
#define Em    8
#define CAP   2048

// ---------------- scratch (static device globals) ----------------
__device__ int   g_count[Em];
__device__ int   g_list[Em * CAP];
__device__ float g_wt[2 * T_TOK];

__device__ __align__(16) __half g_w1h[Em * Hm * Dm];
__device__ __align__(16) __half g_w2h[Em * Dm * Hm];
__device__ __align__(16) __half g_xh[Em * CAP * Dm];
__device__ __align__(16) __half g_hh[Em * CAP * Hm];

// ---------------- PTX helpers ----------------
__device__ __forceinline__ uint32_t smem_u32(const void* p) {
    uint32_t a;
    asm("{ .reg .u64 t; cvta.to.shared.u64 t, %1; cvt.u32.u64 %0, t; }" : "=r"(a) : "l"(p));
    return a;
}
__device__ __forceinline__ void cp16(uint32_t dst, const void* src) {
    asm volatile("cp.async.cg.shared.global [%0], [%1], 16;" :: "r"(dst), "l"(src));
}
#define CP_COMMIT() asm volatile("cp.async.commit_group;" ::: "memory")
#define CP_WAIT(n)  asm volatile("cp.async.wait_group %0;" :: "n"(n) : "memory")

__device__ __forceinline__ uint32_t swz(uint32_t off) { return off ^ ((off >> 3) & 0x70); }

__device__ __forceinline__ void ldm_x4(uint32_t* r, uint32_t addr) {
    asm volatile("ldmatrix.sync.aligned.m8n8.x4.shared.b16 {%0,%1,%2,%3}, [%4];"
                 : "=r"(r[0]), "=r"(r[1]), "=r"(r[2]), "=r"(r[3]) : "r"(addr));
}
__device__ __forceinline__ void mma16816(float* c, const uint32_t* a, uint32_t b0, uint32_t b1) {
    asm volatile("mma.sync.aligned.m16n8k16.row.col.f32.f16.f16.f32 "
                 "{%0,%1,%2,%3}, {%4,%5,%6,%7}, {%8,%9}, {%0,%1,%2,%3};"
                 : "+f"(c[0]), "+f"(c[1]), "+f"(c[2]), "+f"(c[3])
                 : "r"(a[0]), "r"(a[1]), "r"(a[2]), "r"(a[3]), "r"(b0), "r"(b1));
}

// 128-row x 64-col fp16 tile -> SW128 swizzled smem (256 threads, 4 iters)
__device__ __forceinline__ void stage_tile128(uint32_t sbase, const __half* src,
                                              int stride, int tid) {
#pragma unroll
    for (int q4 = 0; q4 < 4; q4++) {
        int q = tid + q4 * 256;
        int r = q >> 3, c = q & 7;
        cp16(sbase + swz((uint32_t)(r * 128 + c * 16)), src + (size_t)r * stride + c * 8);
    }
}

// ---------------- helpers for prep ----------------
__device__ __forceinline__ void conv_two(const float* src, __half* hi, int g0) {
    const int g1 = g0 + 256;
    const float4* s0 = (const float4*)src + (size_t)g0 * 2;
    const float4* s1 = (const float4*)src + (size_t)g1 * 2;
    float4 a0 = s0[0], b0 = s0[1], a1 = s1[0], b1 = s1[1];
    float f0[8] = {a0.x, a0.y, a0.z, a0.w, b0.x, b0.y, b0.z, b0.w};
    float f1[8] = {a1.x, a1.y, a1.z, a1.w, b1.x, b1.y, b1.z, b1.w};
    alignas(16) __half h0[8], h1[8];
#pragma unroll
    for (int j = 0; j < 8; j++) h0[j] = __float2half_rn(f0[j]);
#pragma unroll
    for (int j = 0; j < 8; j++) h1[j] = __float2half_rn(f1[j]);
    *(uint4*)(hi + (size_t)g0 * 8) = *(uint4*)h0;
    *(uint4*)(hi + (size_t)g1 * 8) = *(uint4*)h1;
}

// w2 conversion only (side stream, overlapped with router/w1/fc1)
__global__ __launch_bounds__(256) void convw2_kernel(const float* __restrict__ w2) {
    conv_two(w2, g_w2h, blockIdx.x * 512 + threadIdx.x);
}

// ---------------- fused router + w1 conversion ----------------
__global__ __launch_bounds__(256) void prep_router_kernel(const float* __restrict__ x,
                                                          const float* __restrict__ wr,
                                                          const float* __restrict__ br,
                                                          const float* __restrict__ w1,
                                                          float* __restrict__ logits_out) {
    const int b = blockIdx.x;
    if (b >= 128) {
        conv_two(w1, g_w1h, (b - 128) * 512 + threadIdx.x);
        return;
    }

    const int warp = threadIdx.x >> 5;
    const int lane = threadIdx.x & 31;
    const int t0 = (b * 8 + warp) * 2;

    float4 xv[2][4];
#pragma unroll
    for (int s = 0; s < 2; s++) {
        const float4* xv4 = (const float4*)(x) + (size_t)(t0 + s) * (Dm / 4);
#pragma unroll
        for (int i = 0; i < 4; i++) xv[s][i] = xv4[i * 32 + lane];
    }

    float acc[2][Em];
#pragma unroll
    for (int e = 0; e < Em; e++) {
        const float4* wv4 = (const float4*)(wr) + (size_t)e * (Dm / 4);
        float4 wv[4];
#pragma unroll
        for (int i = 0; i < 4; i++) wv[i] = wv4[i * 32 + lane];
#pragma unroll
        for (int s = 0; s < 2; s++) {
            float a = 0.f;
#pragma unroll
            for (int i = 0; i < 4; i++)
                a += xv[s][i].x * wv[i].x + xv[s][i].y * wv[i].y
                   + xv[s][i].z * wv[i].z + xv[s][i].w * wv[i].w;
            acc[s][e] = a;
        }
    }
#pragma unroll
    for (int off = 16; off > 0; off >>= 1)
#pragma unroll
        for (int s = 0; s < 2; s++)
#pragma unroll
            for (int e = 0; e < Em; e++)
                acc[s][e] += __shfl_xor_sync(0xffffffffu, acc[s][e], off);

#pragma unroll
    for (int s = 0; s < 2; s++) {
        const int t = t0 + s;
        float* lg = acc[s];
#pragma unroll
        for (int e = 0; e < Em; e++) lg[e] += br[e];

        int pack0 = 0, pack1 = 0;
        if (lane == 0) {
            *(float4*)(logits_out + (size_t)t * Em)     = make_float4(lg[0], lg[1], lg[2], lg[3]);
            *(float4*)(logits_out + (size_t)t * Em + 4) = make_float4(lg[4], lg[5], lg[6], lg[7]);
            float mx = lg[0];
#pragma unroll
            for (int e = 1; e < Em; e++) mx = fmaxf(mx, lg[e]);
            float p[Em]; float sum = 0.f;
#pragma unroll
            for (int e = 0; e < Em; e++) { p[e] = expf(lg[e] - mx); sum += p[e]; }
            float inv = 1.0f / sum;
#pragma unroll
            for (int e = 0; e < Em; e++) p[e] *= inv;
            int e0 = 0;
#pragma unroll
            for (int e = 1; e < Em; e++) if (p[e] > p[e0]) e0 = e;
            int e1 = (e0 == 0) ? 1 : 0;
#pragma unroll
            for (int e = 0; e < Em; e++) if (e != e0 && p[e] > p[e1]) e1 = e;
            float sum2 = p[e0] + p[e1];
            g_wt[2 * t + 0] = p[e0] / sum2;
            g_wt[2 * t + 1] = p[e1] / sum2;
            int pos0 = atomicAdd(&g_count[e0], 1);
            g_list[e0 * CAP + pos0] = 2 * t + 0;
            int pos1 = atomicAdd(&g_count[e1], 1);
            g_list[e1 * CAP + pos1] = 2 * t + 1;
            pack0 = (e0 << 16) | pos0;
            pack1 = (e1 << 16) | pos1;
        }
        pack0 = __shfl_sync(0xffffffffu, pack0, 0);
        pack1 = __shfl_sync(0xffffffffu, pack1, 0);
        const int e0 = pack0 >> 16, pos0 = pack0 & 0xffff;
        const int e1 = pack1 >> 16, pos1 = pack1 & 0xffff;

        __half* dh0 = g_xh + ((size_t)e0 * CAP + pos0) * Dm;
        __half* dh1 = g_xh + ((size_t)e1 * CAP + pos1) * Dm;
#pragma unroll
        for (int i = 0; i < 4; i++) {
            float f[4] = {xv[s][i].x, xv[s][i].y, xv[s][i].z, xv[s][i].w};
            alignas(8) __half h[4];
#pragma unroll
            for (int j = 0; j < 4; j++) h[j] = __float2half_rn(f[j]);
            int eo = (i * 32 + lane) * 4;
            *(uint2*)(dh0 + eo) = *(uint2*)h;
            *(uint2*)(dh1 + eo) = *(uint2*)h;
        }
    }
}

// ---------------- GEMM mainloop: 256 thr, CTA 128x128, 3 buffers, occ 2 ----------------
// One barrier per k-tile (top barrier of iter i orders compute(i-1) before staging into
// the same buffer). Warp-staggered kk order.
extern __shared__ char smx[];

#define STAGE_J(kt, bufi)                                                             \
    do {                                                                              \
        uint32_t sb2_ = smb + (bufi) * 32768;                                         \
        stage_tile128(sb2_,         Abase + aoff + (kt) * 64, STRIDE, tid);           \
        stage_tile128(sb2_ + 16384, Bbase + boff + (kt) * 64, STRIDE, tid);           \
        CP_COMMIT();                                                                  \
    } while (0)

#define GEMM_MAINLOOP(NT, STRIDE_V, JOFF)                                             \
    enum { STRIDE = STRIDE_V };                                                       \
    uint32_t smb = smem_u32(smx);                                                     \
    STAGE_J((JOFF) + 0, 0);                                                           \
    STAGE_J((JOFF) + 1, 1);                                                           \
    float acc[4][4][4];                                                               \
    _Pragma("unroll") for (int a1 = 0; a1 < 4; a1++)                                  \
    _Pragma("unroll") for (int a2 = 0; a2 < 4; a2++)                                  \
    _Pragma("unroll") for (int a3 = 0; a3 < 4; a3++) acc[a1][a2][a3] = 0.f;           \
    const int lr = lane & 15, lc = lane >> 4;                                         \
    int bc = 0, bs = 2;                                                               \
    for (int i = 0; i < NT; i++) {                                                    \
        if (i < NT - 1) CP_WAIT(1); else CP_WAIT(0);                                  \
        __syncthreads();                                                              \
        if (i + 2 < NT) { STAGE_J((JOFF) + i + 2, bs); bs = (bs == 2) ? 0 : bs + 1; } \
        uint32_t sa = smb + bc * 32768, sbb = sa + 16384;                             \
        bc = (bc == 2) ? 0 : bc + 1;                                                  \
        _Pragma("unroll")                                                             \
        for (int kk16 = 0; kk16 < 4; kk16++) {                                        \
            const int kidx = (kk16 + warpM) & 3;                                      \
            uint32_t af[4][4];                                                        \
            _Pragma("unroll")                                                         \
            for (int mi = 0; mi < 4; mi++) {                                          \
                uint32_t off = (uint32_t)((warpM * 64 + mi * 16 + lr) * 128           \
                                          + (kidx * 2 + lc) * 16);                    \
                ldm_x4(af[mi], sa + swz(off));                                        \
            }                                                                         \
            uint32_t bfr[2][4];                                                       \
            _Pragma("unroll")                                                         \
            for (int nj = 0; nj < 2; nj++) {                                          \
                uint32_t off = (uint32_t)((warpN * 32 + nj * 16 + lr) * 128           \
                                          + (kidx * 2 + lc) * 16);                    \
                ldm_x4(bfr[nj], sbb + swz(off));                                      \
            }                                                                         \
            _Pragma("unroll")                                                         \
            for (int mi = 0; mi < 4; mi++)                                            \
                _Pragma("unroll")                                                     \
                for (int ni = 0; ni < 4; ni++) {                                      \
                    const int nj = ni >> 1, sub = ni & 1;                             \
                    mma16816(acc[mi][ni], af[mi], bfr[nj][sub], bfr[nj][sub + 2]);    \
                }                                                                     \
        }                                                                             \
    }

// ---------------- fc1: h = gelu(X @ W1^T), CTA 128x128, single fp16 pass ----------------
__global__ __launch_bounds__(256, 2) void fc1_kernel() {
    const int e = blockIdx.z;
    const int cnt = g_count[e];
    const int rowbase = blockIdx.y * 128;
    if (rowbase >= cnt) return;
    const int nbase = blockIdx.x * 128;

    const int tid = threadIdx.x;
    const int wid = tid >> 5, lane = tid & 31;
    const int warpM = wid >> 2, warpN = wid & 3;

    const __half* Abase = g_xh;
    const __half* Bbase = g_w1h;
    const size_t aoff = ((size_t)e * CAP + rowbase) * Dm;
    const size_t boff = ((size_t)e * Hm + nbase) * Dm;

    GEMM_MAINLOOP(8, Dm, 0)   // K = 512

    const int r0 = lane >> 2, c0 = (lane & 3) * 2;
#pragma unroll
    for (int mi = 0; mi < 4; mi++) {
#pragma unroll
        for (int half = 0; half < 2; half++) {
            int row = rowbase + warpM * 64 + mi * 16 + r0 + half * 8;
            size_t rg = ((size_t)e * CAP + row) * Hm + nbase + warpN * 32 + c0;
#pragma unroll
            for (int ni = 0; ni < 4; ni++) {
                float v0 = acc[mi][ni][half * 2 + 0];
                float v1 = acc[mi][ni][half * 2 + 1];
                float gg0 = 0.5f * v0 * (1.0f + erff(v0 * 0.70710678118654752f));
                float gg1 = 0.5f * v1 * (1.0f + erff(v1 * 0.70710678118654752f));
                __half h0 = __float2half_rn(gg0);
                __half h1 = __float2half_rn(gg1);
                uint32_t hp = (uint32_t)*(uint16_t*)&h0 | ((uint32_t)*(uint16_t*)&h1 << 16);
                *(uint32_t*)(g_hh + rg + ni * 8) = hp;
            }
        }
    }
}

// ---------------- fc2: out[tok] += w * (H @ W2^T), split-K x2 ----------------
__global__ __launch_bounds__(256, 2) void fc2_kernel(float* __restrict__ out) {
    const int e = blockIdx.z;
    const int cnt = g_count[e];
    const int rowbase = blockIdx.y * 128;
    if (rowbase >= cnt) return;
    const int ksplit = blockIdx.x >> 2;
    const int nbase = (blockIdx.x & 3) * 128;

    const int tid = threadIdx.x;
    const int wid = tid >> 5, lane = tid & 31;
    const int warpM = wid >> 2, warpN = wid & 3;

    const __half* Abase = g_hh;
    const __half* Bbase = g_w2h;
    const size_t aoff = ((size_t)e * CAP + rowbase) * Hm;
    const size_t boff = ((size_t)e * Dm + nbase) * Hm;

    GEMM_MAINLOOP(8, Hm, ksplit * 8)   // halves of K=1024

    const int r0 = lane >> 2, c0 = (lane & 3) * 2;
#pragma unroll
    for (int mi = 0; mi < 4; mi++) {
#pragma unroll
        for (int half = 0; half < 2; half++) {
            int pos = rowbase + warpM * 64 + mi * 16 + r0 + half * 8;
            if (pos >= cnt) continue;
            int entry = g_list[e * CAP + pos];
            float w = g_wt[entry];
            int tok = entry >> 1;
            float* op = out + (size_t)tok * Dm + nbase + warpN * 32 + c0;
#pragma unroll
            for (int ni = 0; ni < 4; ni++) {
                atomicAdd(op + ni * 8,     w * acc[mi][ni][half * 2 + 0]);
                atomicAdd(op + ni * 8 + 1, w * acc[mi][ni][half * 2 + 1]);
            }
        }
    }
}

// ---------------- launch ----------------
extern "C" void kernel_launch(void* const* d_in, const int* in_sizes, int n_in,
                              void* d_out, int out_size) {
    const float* x  = (const float*)d_in[0];
    const float* wr = (const float*)d_in[1];
    const float* br = (const float*)d_in[2];
    const float* w1 = (const float*)d_in[3];
    const float* w2 = (const float*)d_in[4];
    float* out = (float*)d_out;
    float* logits = out + (size_t)T_TOK * Dm;

    static void* count_ptr = nullptr;
    static cudaStream_t s2 = nullptr;
    static cudaEvent_t evFork = nullptr, evJoin = nullptr;
    static int init_done = 0;
    if (!init_done) {
        cudaFuncSetAttribute(fc1_kernel, cudaFuncAttributeMaxDynamicSharedMemorySize, 98304);
        cudaFuncSetAttribute(fc2_kernel, cudaFuncAttributeMaxDynamicSharedMemorySize, 98304);
        cudaGetSymbolAddress(&count_ptr, g_count);
        cudaStreamCreateWithFlags(&s2, cudaStreamNonBlocking);
        cudaEventCreateWithFlags(&evFork, cudaEventDisableTiming);
        cudaEventCreateWithFlags(&evJoin, cudaEventDisableTiming);
        init_done = 1;
    }

    // main stream: counts memset -> router+w1 -> fc1
    cudaMemsetAsync(count_ptr, 0, Em * sizeof(int));
    // fork: side stream does w2 conversion + out zeroing, concurrent with router/w1/fc1
    cudaEventRecord(evFork, 0);
    cudaStreamWaitEvent(s2, evFork, 0);
    convw2_kernel<<<1024, 256, 0, s2>>>(w2);
    cudaMemsetAsync(out, 0, (size_t)T_TOK * Dm * sizeof(float), s2);
    cudaEventRecord(evJoin, s2);

    prep_router_kernel<<<1152, 256>>>(x, wr, br, w1, logits);
    dim3 g1(Hm / 128, CAP / 128, Em);          // (8, 16, 8)
    fc1_kernel<<<g1, 256, 98304>>>();

    // join before fc2 (needs w2h + zeroed out)
    cudaStreamWaitEvent(0, evJoin, 0);
    dim3 g2((Dm / 128) * 2, CAP / 128, Em);    // (8, 16, 8)
    fc2_kernel<<<g2, 256, 98304>>>(out);
}